// round 16
// baseline (speedup 1.0000x reference)
#include <cuda_runtime.h>
#include <cuda_bf16.h>
#include <math.h>
#include <cstdint>

// Problem constants
#define BB 4
#define NN 2048
#define CC 512
#define HH 8
#define DD 64
#define TT (BB*NN)          // 8192 tokens
#define FF 2048             // d_ff

// ---------------------------------------------------------------------------
// Scratch layout (float units)
#define OFF_S     0ull          // fp32 [TT, C]
#define OFF_GATE  4194304ull    // fp32 [TT, C]
#define OFF_X1    8388608ull    // fp32 [TT, C]
#define OFF_XNB   12582912ull   // bf16 [TT, C]
#define OFF_ENB   14680064ull   // bf16 [TT, C]
#define OFF_XN3B  16777216ull   // bf16 [TT, C]
#define OFF_AGB   18874368ull   // bf16 [TT, C]
#define OFF_HB    20971520ull   // bf16 [TT, FF]
#define OFF_WQKVG 29360128ull   // bf16 [2048, 512]  (rows: wqkvT 0..1535, wgT 1536..2047)
#define OFF_WST   29884416ull   // bf16 [C, C]
#define OFF_WPT   30015488ull   // bf16 [C, C]
#define OFF_WF1T  30146560ull   // bf16 [FF, C]
#define OFF_WF2T  30670848ull   // bf16 [C, FF]
#define OFF_QH    31195136ull   // bf16 [B*H, N, 64]
#define OFF_KH    33292288ull   // bf16 [B*H, N, 64]
#define OFF_VH    35389440ull   // bf16 [B*H, N, 64]
#define SCRATCH_FLOATS 37486592ull

__device__ float g_scratch[SCRATCH_FLOATS];

// ---------------------------------------------------------------------------
__device__ __forceinline__ uint32_t smem_u32(const void* p) {
    uint32_t a;
    asm("{ .reg .u64 t; cvta.to.shared.u64 t, %1; cvt.u32.u64 %0, t; }" : "=r"(a) : "l"(p));
    return a;
}
__device__ __forceinline__ void cp_async16(uint32_t saddr, const void* gaddr) {
    asm volatile("cp.async.cg.shared.global [%0], [%1], 16;" :: "r"(saddr), "l"(gaddr) : "memory");
}
__device__ __forceinline__ void cp_commit() {
    asm volatile("cp.async.commit_group;" ::: "memory");
}
__device__ __forceinline__ void ldmx4(uint32_t& r0, uint32_t& r1, uint32_t& r2, uint32_t& r3,
                                      uint32_t addr) {
    asm volatile("ldmatrix.sync.aligned.m8n8.x4.shared.b16 {%0,%1,%2,%3}, [%4];"
                 : "=r"(r0), "=r"(r1), "=r"(r2), "=r"(r3) : "r"(addr));
}
__device__ __forceinline__ void ldmx4t(uint32_t& r0, uint32_t& r1, uint32_t& r2, uint32_t& r3,
                                       uint32_t addr) {
    asm volatile("ldmatrix.sync.aligned.m8n8.x4.trans.shared.b16 {%0,%1,%2,%3}, [%4];"
                 : "=r"(r0), "=r"(r1), "=r"(r2), "=r"(r3) : "r"(addr));
}
__device__ __forceinline__ void mma16816(float* c, const uint32_t* a, uint32_t b0, uint32_t b1) {
    asm volatile(
        "mma.sync.aligned.m16n8k16.row.col.f32.bf16.bf16.f32 "
        "{%0,%1,%2,%3}, {%4,%5,%6,%7}, {%8,%9}, {%0,%1,%2,%3};"
        : "+f"(c[0]), "+f"(c[1]), "+f"(c[2]), "+f"(c[3])
        : "r"(a[0]), "r"(a[1]), "r"(a[2]), "r"(a[3]), "r"(b0), "r"(b1));
}
__device__ __forceinline__ uint32_t pack_bf16(float a, float b) {
    __nv_bfloat162 p = __floats2bfloat162_rn(a, b);
    return *(uint32_t*)&p;
}

// ---------------------------------------------------------------------------
// Fused LayerNorm for LN1(x) and LN2(e): blockIdx.y selects.
__global__ void ln2x_kernel(const float* __restrict__ x, const float* __restrict__ e,
                            const float* __restrict__ w1, const float* __restrict__ b1,
                            const float* __restrict__ w2, const float* __restrict__ b2,
                            __nv_bfloat16* __restrict__ y1, __nv_bfloat16* __restrict__ y2) {
    int row = blockIdx.x;
    int which = blockIdx.y;
    const float* src = which ? e : x;
    const float* w   = which ? w2 : w1;
    const float* b   = which ? b2 : b1;
    __nv_bfloat16* y = which ? y2 : y1;
    int tid = threadIdx.x;
    const float4* xr = (const float4*)(src + (size_t)row * CC);
    float4 v = xr[tid];
    float s  = v.x + v.y + v.z + v.w;
    float ss = v.x*v.x + v.y*v.y + v.z*v.z + v.w*v.w;
    #pragma unroll
    for (int off = 16; off; off >>= 1) {
        s  += __shfl_xor_sync(0xffffffffu, s,  off);
        ss += __shfl_xor_sync(0xffffffffu, ss, off);
    }
    __shared__ float sm[4], sm2[4];
    int warp = tid >> 5, lane = tid & 31;
    if (lane == 0) { sm[warp] = s; sm2[warp] = ss; }
    __syncthreads();
    float tot  = sm[0] + sm[1] + sm[2] + sm[3];
    float tot2 = sm2[0] + sm2[1] + sm2[2] + sm2[3];
    float mu   = tot * (1.0f / CC);
    float var  = tot2 * (1.0f / CC) - mu * mu;
    float rstd = rsqrtf(var + 1e-5f);
    float4 wv = ((const float4*)w)[tid];
    float4 bv = ((const float4*)b)[tid];
    uint2 o;
    o.x = pack_bf16((v.x - mu) * rstd * wv.x + bv.x, (v.y - mu) * rstd * wv.y + bv.y);
    o.y = pack_bf16((v.z - mu) * rstd * wv.z + bv.z, (v.w - mu) * rstd * wv.w + bv.w);
    ((uint2*)(y + (size_t)row * CC))[tid] = o;
}

// Single-tensor LN (for LN3)
__global__ void ln_kernel(const float* __restrict__ x,
                          const float* __restrict__ w,
                          const float* __restrict__ b,
                          __nv_bfloat16* __restrict__ y) {
    int row = blockIdx.x;
    int tid = threadIdx.x;
    const float4* xr = (const float4*)(x + (size_t)row * CC);
    float4 v = xr[tid];
    float s  = v.x + v.y + v.z + v.w;
    float ss = v.x*v.x + v.y*v.y + v.z*v.z + v.w*v.w;
    #pragma unroll
    for (int off = 16; off; off >>= 1) {
        s  += __shfl_xor_sync(0xffffffffu, s,  off);
        ss += __shfl_xor_sync(0xffffffffu, ss, off);
    }
    __shared__ float sm[4], sm2[4];
    int warp = tid >> 5, lane = tid & 31;
    if (lane == 0) { sm[warp] = s; sm2[warp] = ss; }
    __syncthreads();
    float tot  = sm[0] + sm[1] + sm[2] + sm[3];
    float tot2 = sm2[0] + sm2[1] + sm2[2] + sm2[3];
    float mu   = tot * (1.0f / CC);
    float var  = tot2 * (1.0f / CC) - mu * mu;
    float rstd = rsqrtf(var + 1e-5f);
    float4 wv = ((const float4*)w)[tid];
    float4 bv = ((const float4*)b)[tid];
    uint2 o;
    o.x = pack_bf16((v.x - mu) * rstd * wv.x + bv.x, (v.y - mu) * rstd * wv.y + bv.y);
    o.y = pack_bf16((v.z - mu) * rstd * wv.z + bv.z, (v.w - mu) * rstd * wv.w + bv.w);
    ((uint2*)(y + (size_t)row * CC))[tid] = o;
}

// ---------------------------------------------------------------------------
// Uber weight-transpose: all 6 weights in one launch. Tile id -> weight.
__global__ void wt_all_kernel(
    const float* __restrict__ w_qkv, const float* __restrict__ w_gate,
    const float* __restrict__ w_s,   const float* __restrict__ w_proj,
    const float* __restrict__ w_fc1, const float* __restrict__ w_fc2,
    __nv_bfloat16* __restrict__ wqkvg, __nv_bfloat16* __restrict__ wsT,
    __nv_bfloat16* __restrict__ wpT,   __nv_bfloat16* __restrict__ wf1T,
    __nv_bfloat16* __restrict__ wf2T)
{
    __shared__ float t[32][33];
    int tb = blockIdx.x;
    const float* W; __nv_bfloat16* WT; int K, N, ntx, loc;
    if (tb < 768)       { W = w_qkv;  WT = wqkvg;                       K = 512;  N = 1536; ntx = 48; loc = tb; }
    else if (tb < 1024) { W = w_gate; WT = wqkvg + (size_t)1536 * 512;  K = 512;  N = 512;  ntx = 16; loc = tb - 768; }
    else if (tb < 1280) { W = w_s;    WT = wsT;                         K = 512;  N = 512;  ntx = 16; loc = tb - 1024; }
    else if (tb < 1536) { W = w_proj; WT = wpT;                         K = 512;  N = 512;  ntx = 16; loc = tb - 1280; }
    else if (tb < 2560) { W = w_fc1;  WT = wf1T;                        K = 512;  N = 2048; ntx = 64; loc = tb - 1536; }
    else                { W = w_fc2;  WT = wf2T;                        K = 2048; N = 512;  ntx = 16; loc = tb - 2560; }
    int n0 = (loc % ntx) * 32, k0 = (loc / ntx) * 32;
    int tx = threadIdx.x, ty = threadIdx.y;   // 32 x 8
    #pragma unroll
    for (int i = 0; i < 32; i += 8)
        t[ty + i][tx] = W[(size_t)(k0 + ty + i) * N + n0 + tx];
    __syncthreads();
    #pragma unroll
    for (int i = 0; i < 32; i += 8)
        WT[(size_t)(n0 + ty + i) * K + k0 + tx] = __float2bfloat16(t[tx][ty + i]);
}

// ---------------------------------------------------------------------------
// mm2: HMMA bf16 GEMM, 128x128 CTA tile, 256 threads (8 warps, 2x4, 64x32
// warp tiles), BK=64 (128B rows, stride 144), 3-stage cp.async, 2 CTAs/SM.
#define M2_ROW  144
#define M2_B    18432           // A: 128 rows; B at row 128
#define M2_STG  36864           // 256 * 144
#define M2_NSTG 3
#define M2_SMEM (M2_NSTG * M2_STG)   // 110592

template<int MODE>
__global__ void __launch_bounds__(256, 2) mm2_kernel(
    const __nv_bfloat16* __restrict__ A,   // [M,K]
    const __nv_bfloat16* __restrict__ Bt,  // [N,K]
    const float* __restrict__ bias,
    const float* __restrict__ res,
    const float* __restrict__ sextra,      // MODE 2: s [TT, 512]
    float* __restrict__ outf,              // MODE 0 / MODE 2 gate
    __nv_bfloat16* __restrict__ outb0,     // MODE 1 out / MODE 2 qh
    __nv_bfloat16* __restrict__ outb1,     // MODE 2 kh
    __nv_bfloat16* __restrict__ outb2,     // MODE 2 vh
    int M, int N, int K)
{
    extern __shared__ __align__(16) char smem[];
    uint32_t sb = smem_u32(smem);

    int tid = threadIdx.x, wid = tid >> 5, lane = tid & 31;
    int m0 = blockIdx.y * 128, n0 = blockIdx.x * 128;
    int wm = wid & 1, wn = wid >> 1;        // 2 x 4 warps, 64x32 each

    const char* Abase = (const char*)A;
    const char* Bbase = (const char*)Bt;
    size_t rstride = (size_t)K * 2;
    int KC = K >> 6;   // BK = 64

    auto load_tile = [&](int kc, int stg) {
        uint32_t base = sb + stg * M2_STG;
        size_t koff = (size_t)kc * 128;
        #pragma unroll
        for (int i = 0; i < 8; i++) {
            int idx = i * 256 + tid;         // 0..2047
            int row = idx >> 3;              // 0..255
            int c = (idx & 7) * 16;
            const char* g = (row < 128)
                ? Abase + (size_t)(m0 + row) * rstride + koff + c
                : Bbase + (size_t)(n0 + row - 128) * rstride + koff + c;
            cp_async16(base + row * M2_ROW + c, g);
        }
        cp_commit();
    };

    float acc[4][4][4];
    #pragma unroll
    for (int mi = 0; mi < 4; mi++)
        #pragma unroll
        for (int nb = 0; nb < 4; nb++)
            #pragma unroll
            for (int j = 0; j < 4; j++) acc[mi][nb][j] = 0.f;

    load_tile(0, 0);
    load_tile(1, 1);

    uint32_t lrow16 = (lane & 15);
    uint32_t lkhalf = (lane >> 4) * 16;

    for (int kc = 0; kc < KC; kc++) {
        if (kc < KC - 1) asm volatile("cp.async.wait_group 1;" ::: "memory");
        else             asm volatile("cp.async.wait_group 0;" ::: "memory");
        __syncthreads();

        if (kc + 2 < KC) load_tile(kc + 2, (kc + 2) % M2_NSTG);

        int stg = kc % M2_NSTG;
        uint32_t sA = sb + stg * M2_STG + (wm * 64 + lrow16) * M2_ROW + lkhalf;
        uint32_t sB = sb + stg * M2_STG + M2_B + (wn * 32 + lrow16) * M2_ROW + lkhalf;

        #pragma unroll
        for (int ks = 0; ks < 4; ks++) {
            uint32_t koff = ks * 32;
            uint32_t a[4][4];
            #pragma unroll
            for (int mi = 0; mi < 4; mi++)
                ldmx4(a[mi][0], a[mi][1], a[mi][2], a[mi][3],
                      sA + mi * 16 * M2_ROW + koff);
            uint32_t b[2][4];
            #pragma unroll
            for (int nb = 0; nb < 2; nb++)
                ldmx4(b[nb][0], b[nb][1], b[nb][2], b[nb][3],
                      sB + nb * 16 * M2_ROW + koff);
            #pragma unroll
            for (int mi = 0; mi < 4; mi++)
                #pragma unroll
                for (int nb = 0; nb < 2; nb++) {
                    mma16816(acc[mi][nb * 2 + 0], a[mi], b[nb][0], b[nb][2]);
                    mma16816(acc[mi][nb * 2 + 1], a[mi], b[nb][1], b[nb][3]);
                }
        }
        // no bottom barrier (overwrite of a stage is a cp.async issued after
        // a later full barrier + global-load flight time past its last read)
    }

    // ---- epilogue ----
    int mbase = m0 + wm * 64 + (lane >> 2);
    int nbase = n0 + wn * 32 + (lane & 3) * 2;
    int seg = nbase >> 9;          // uniform per warp (MODE 2)

    #pragma unroll
    for (int mi = 0; mi < 4; mi++) {
        #pragma unroll
        for (int nb = 0; nb < 4; nb++) {
            int n = nbase + nb * 8;
            #pragma unroll
            for (int half = 0; half < 2; half++) {
                int m = mbase + mi * 16 + half * 8;
                float v0 = acc[mi][nb][half * 2 + 0];
                float v1 = acc[mi][nb][half * 2 + 1];
                if (MODE == 0) {
                    if (bias) { v0 += bias[n]; v1 += bias[n + 1]; }
                    if (res) {
                        const float* rp = res + (size_t)m * N + n;
                        v0 += rp[0]; v1 += rp[1];
                    }
                    *(float2*)(outf + (size_t)m * N + n) = make_float2(v0, v1);
                } else if (MODE == 1) {
                    v0 += bias[n]; v1 += bias[n + 1];
                    v0 = 0.5f * v0 * (1.0f + erff(v0 * 0.70710678118654752f));
                    v1 = 0.5f * v1 * (1.0f + erff(v1 * 0.70710678118654752f));
                    *(uint32_t*)(outb0 + (size_t)m * N + n) = pack_bf16(v0, v1);
                } else {
                    int c = n & 511;
                    int bidx = m >> 11, nloc = m & (NN - 1);
                    if (seg == 3) {
                        *(float2*)(outf + (size_t)m * CC + c) = make_float2(v0, v1);
                    } else {
                        int h = c >> 6, d = c & 63;
                        size_t ph = (((size_t)(bidx * HH + h) * NN + nloc) << 6) + d;
                        if (seg == 0) {
                            *(uint32_t*)(outb0 + ph) = pack_bf16(v0 * 0.125f, v1 * 0.125f);
                        } else if (seg == 1) {
                            float2 sv = *(const float2*)(sextra + (size_t)m * CC + c);
                            *(uint32_t*)(outb1 + ph) = pack_bf16(v0 + sv.x, v1 + sv.y);
                        } else {
                            *(uint32_t*)(outb2 + ph) = pack_bf16(v0, v1);
                        }
                    }
                }
            }
        }
    }
}

// ---------------------------------------------------------------------------
// bf16 HMMA flash attention, fused gate-multiply epilogue.
// 128-key double KV tiles: one cp.async stage + one barrier per 128 keys;
// each tile processed as two 64-key halves (identical math/register shape
// as the 64-key version -> bit-identical results).
#define AT_QOFF 0
#define AT_ROW  144
#define AT_KV0  18432
#define AT_STG  36864           // K 128 rows + V 128 rows, 144B stride
#define AT_VOFF 18432           // V offset within a stage
#define AT_SMEM (18432 + 2 * 36864)   // 92160

__global__ void __launch_bounds__(256) attn_kernel(
    const __nv_bfloat16* __restrict__ qh,
    const __nv_bfloat16* __restrict__ kh,
    const __nv_bfloat16* __restrict__ vh,
    const float* __restrict__ gate,
    __nv_bfloat16* __restrict__ outb)
{
    extern __shared__ char smem[];
    uint32_t sb = smem_u32(smem);
    int tid = threadIdx.x, wid = tid >> 5, lane = tid & 31;
    int qt = blockIdx.x, h = blockIdx.y, b = blockIdx.z;
    int bh = b * HH + h;
    int tq0 = qt * 128;

    const char* Qg = (const char*)(qh + (((size_t)bh * NN + tq0) << 6));
    const char* Kg = (const char*)(kh + ((size_t)bh * NN << 6));
    const char* Vg = (const char*)(vh + ((size_t)bh * NN << 6));

    for (int i = tid; i < 1024; i += 256) {
        int r = i >> 3, c = (i & 7) * 16;
        cp_async16(sb + AT_QOFF + r * AT_ROW + c, Qg + (size_t)r * 128 + c);
    }
    cp_commit();

    // load 128 keys + 128 values into one stage
    auto loadKV = [&](int kt2, int stg) {
        const char* K0 = Kg + ((size_t)kt2 << 14);   // kt2*128*64*2
        const char* V0 = Vg + ((size_t)kt2 << 14);
        uint32_t ks = sb + AT_KV0 + stg * AT_STG;
        for (int i = tid; i < 1024; i += 256) {
            int r = i >> 3, c = (i & 7) * 16;
            cp_async16(ks + r * AT_ROW + c, K0 + (size_t)r * 128 + c);
            cp_async16(ks + AT_VOFF + r * AT_ROW + c, V0 + (size_t)r * 128 + c);
        }
        cp_commit();
    };

    loadKV(0, 0);
    asm volatile("cp.async.wait_group 0;" ::: "memory");
    __syncthreads();

    int r0 = wid * 16;
    uint32_t qf[4][4];
    {
        uint32_t base = sb + AT_QOFF + (r0 + (lane & 15)) * AT_ROW + (lane >> 4) * 16;
        #pragma unroll
        for (int kb = 0; kb < 4; kb++)
            ldmx4(qf[kb][0], qf[kb][1], qf[kb][2], qf[kb][3], base + kb * 32);
    }

    float o[8][4];
    #pragma unroll
    for (int nd = 0; nd < 8; nd++)
        #pragma unroll
        for (int j = 0; j < 4; j++) o[nd][j] = 0.f;
    float m0 = -1e30f, m1 = -1e30f, l0 = 0.f, l1 = 0.f;

    int j2 = lane >> 3;
    int rin = lane & 7;

    const int KT2 = NN / 128;   // 16 double tiles
    for (int kt2 = 0; kt2 < KT2; kt2++) {
        int stg = kt2 & 1;
        if (kt2 + 1 < KT2) {
            asm volatile("cp.async.wait_group 1;" ::: "memory");
        } else {
            asm volatile("cp.async.wait_group 0;" ::: "memory");
        }
        __syncthreads();

        if (kt2 + 1 < KT2) loadKV(kt2 + 1, stg ^ 1);

        #pragma unroll
        for (int half64 = 0; half64 < 2; half64++) {
            uint32_t Kst = sb + AT_KV0 + stg * AT_STG + half64 * 64 * AT_ROW;
            uint32_t Vst = sb + AT_KV0 + stg * AT_STG + AT_VOFF + half64 * 64 * AT_ROW;

            float sc[8][4];
            #pragma unroll
            for (int nb = 0; nb < 8; nb++)
                #pragma unroll
                for (int j = 0; j < 4; j++) sc[nb][j] = 0.f;

            #pragma unroll
            for (int p = 0; p < 4; p++) {
                #pragma unroll
                for (int kb = 0; kb < 4; kb++) {
                    uint32_t addr = Kst + (p * 16 + (j2 >> 1) * 8 + rin) * AT_ROW
                                        + kb * 32 + (j2 & 1) * 16;
                    uint32_t b0, b1, b2, b3;
                    ldmx4(b0, b1, b2, b3, addr);
                    mma16816(sc[2 * p + 0], qf[kb], b0, b1);
                    mma16816(sc[2 * p + 1], qf[kb], b2, b3);
                }
            }

            float mx0 = -1e30f, mx1 = -1e30f;
            #pragma unroll
            for (int nb = 0; nb < 8; nb++) {
                mx0 = fmaxf(mx0, fmaxf(sc[nb][0], sc[nb][1]));
                mx1 = fmaxf(mx1, fmaxf(sc[nb][2], sc[nb][3]));
            }
            mx0 = fmaxf(mx0, __shfl_xor_sync(0xffffffffu, mx0, 1));
            mx0 = fmaxf(mx0, __shfl_xor_sync(0xffffffffu, mx0, 2));
            mx1 = fmaxf(mx1, __shfl_xor_sync(0xffffffffu, mx1, 1));
            mx1 = fmaxf(mx1, __shfl_xor_sync(0xffffffffu, mx1, 2));

            float mn0 = fmaxf(m0, mx0), mn1 = fmaxf(m1, mx1);
            float corr0 = __expf(m0 - mn0), corr1 = __expf(m1 - mn1);
            m0 = mn0; m1 = mn1;

            uint32_t pa[8], pb[8];
            float sum0 = 0.f, sum1 = 0.f;
            #pragma unroll
            for (int nb = 0; nb < 8; nb++) {
                float p0 = __expf(sc[nb][0] - mn0);
                float p1 = __expf(sc[nb][1] - mn0);
                float p2 = __expf(sc[nb][2] - mn1);
                float p3 = __expf(sc[nb][3] - mn1);
                sum0 += p0 + p1; sum1 += p2 + p3;
                pa[nb] = pack_bf16(p0, p1);
                pb[nb] = pack_bf16(p2, p3);
            }
            sum0 += __shfl_xor_sync(0xffffffffu, sum0, 1);
            sum0 += __shfl_xor_sync(0xffffffffu, sum0, 2);
            sum1 += __shfl_xor_sync(0xffffffffu, sum1, 1);
            sum1 += __shfl_xor_sync(0xffffffffu, sum1, 2);
            l0 = l0 * corr0 + sum0;
            l1 = l1 * corr1 + sum1;

            #pragma unroll
            for (int nd = 0; nd < 8; nd++) {
                o[nd][0] *= corr0; o[nd][1] *= corr0;
                o[nd][2] *= corr1; o[nd][3] *= corr1;
            }

            #pragma unroll
            for (int kb = 0; kb < 4; kb++) {
                uint32_t a[4] = { pa[2 * kb], pb[2 * kb], pa[2 * kb + 1], pb[2 * kb + 1] };
                #pragma unroll
                for (int v = 0; v < 4; v++) {
                    uint32_t addr = Vst + (kb * 16 + (j2 & 1) * 8 + rin) * AT_ROW
                                        + v * 32 + (j2 >> 1) * 16;
                    uint32_t b0, b1, b2, b3;
                    ldmx4t(b0, b1, b2, b3, addr);
                    mma16816(o[2 * v + 0], a, b0, b1);
                    mma16816(o[2 * v + 1], a, b2, b3);
                }
            }
        }
        // no bottom barrier (same stage-overwrite argument as mm2)
    }

    float inv0 = 1.0f / l0, inv1 = 1.0f / l1;
    int rowa = tq0 + r0 + (lane >> 2);
    size_t toka = (size_t)b * NN + rowa;
    size_t tokb = toka + 8;
    int cb = h * DD + (lane & 3) * 2;
    #pragma unroll
    for (int nd = 0; nd < 8; nd++) {
        int d = cb + nd * 8;
        float2 ga = *(const float2*)(gate + toka * CC + d);
        float2 gb = *(const float2*)(gate + tokb * CC + d);
        *(uint32_t*)(outb + toka * CC + d) = pack_bf16(o[nd][0] * inv0 * ga.x,
                                                       o[nd][1] * inv0 * ga.y);
        *(uint32_t*)(outb + tokb * CC + d) = pack_bf16(o[nd][2] * inv1 * gb.x,
                                                       o[nd][3] * inv1 * gb.y);
    }
}

// ---------------------------------------------------------------------------
extern "C" void kernel_launch(void* const* d_in, const int* in_sizes, int n_in,
                              void* d_out, int out_size) {
    const float* x      = (const float*)d_in[0];
    const float* e      = (const float*)d_in[1];
    const float* w_qkv  = (const float*)d_in[2];
    const float* w_s    = (const float*)d_in[3];
    const float* w_gate = (const float*)d_in[4];
    const float* w_proj = (const float*)d_in[5];
    const float* b_proj = (const float*)d_in[6];
    const float* ln1_w  = (const float*)d_in[7];
    const float* ln1_b  = (const float*)d_in[8];
    const float* ln2_w  = (const float*)d_in[9];
    const float* ln2_b  = (const float*)d_in[10];
    const float* ln3_w  = (const float*)d_in[11];
    const float* ln3_b  = (const float*)d_in[12];
    const float* w_fc1  = (const float*)d_in[13];
    const float* b_fc1  = (const float*)d_in[14];
    const float* w_fc2  = (const float*)d_in[15];
    const float* b_fc2  = (const float*)d_in[16];
    float* out = (float*)d_out;

    void* scr_v = nullptr;
    cudaGetSymbolAddress(&scr_v, g_scratch);
    float* scr = (float*)scr_v;
    float*         g_s    = scr + OFF_S;
    float*         g_gate = scr + OFF_GATE;
    float*         g_x1   = scr + OFF_X1;
    __nv_bfloat16* g_xnb  = (__nv_bfloat16*)(scr + OFF_XNB);
    __nv_bfloat16* g_enb  = (__nv_bfloat16*)(scr + OFF_ENB);
    __nv_bfloat16* g_xn3b = (__nv_bfloat16*)(scr + OFF_XN3B);
    __nv_bfloat16* g_agb  = (__nv_bfloat16*)(scr + OFF_AGB);
    __nv_bfloat16* g_hb   = (__nv_bfloat16*)(scr + OFF_HB);
    __nv_bfloat16* wqkvg  = (__nv_bfloat16*)(scr + OFF_WQKVG);
    __nv_bfloat16* wsT    = (__nv_bfloat16*)(scr + OFF_WST);
    __nv_bfloat16* wpT    = (__nv_bfloat16*)(scr + OFF_WPT);
    __nv_bfloat16* wf1T   = (__nv_bfloat16*)(scr + OFF_WF1T);
    __nv_bfloat16* wf2T   = (__nv_bfloat16*)(scr + OFF_WF2T);
    __nv_bfloat16* g_qh   = (__nv_bfloat16*)(scr + OFF_QH);
    __nv_bfloat16* g_kh   = (__nv_bfloat16*)(scr + OFF_KH);
    __nv_bfloat16* g_vh   = (__nv_bfloat16*)(scr + OFF_VH);

    cudaFuncSetAttribute(attn_kernel, cudaFuncAttributeMaxDynamicSharedMemorySize, AT_SMEM);
    cudaFuncSetAttribute(mm2_kernel<0>, cudaFuncAttributeMaxDynamicSharedMemorySize, M2_SMEM);
    cudaFuncSetAttribute(mm2_kernel<1>, cudaFuncAttributeMaxDynamicSharedMemorySize, M2_SMEM);
    cudaFuncSetAttribute(mm2_kernel<2>, cudaFuncAttributeMaxDynamicSharedMemorySize, M2_SMEM);

    // all weight transposes in one launch
    wt_all_kernel<<<3584, dim3(32, 8)>>>(w_qkv, w_gate, w_s, w_proj, w_fc1, w_fc2,
                                         wqkvg, wsT, wpT, wf1T, wf2T);

    // LN1(x) and LN2(e) in one launch
    ln2x_kernel<<<dim3(TT, 2), 128>>>(x, e, ln1_w, ln1_b, ln2_w, ln2_b, g_xnb, g_enb);

    // s = en @ w_s  (fp32, needed by qkvg epilogue)
    mm2_kernel<0><<<dim3(CC / 128, TT / 128), 256, M2_SMEM>>>(
        g_enb, wsT, nullptr, nullptr, nullptr, g_s, nullptr, nullptr, nullptr,
        TT, CC, CC);

    // fused qkv+gate GEMM with per-head scatter epilogue
    mm2_kernel<2><<<dim3(2048 / 128, TT / 128), 256, M2_SMEM>>>(
        g_xnb, wqkvg, nullptr, nullptr, g_s, g_gate, g_qh, g_kh, g_vh,
        TT, 2048, CC);

    attn_kernel<<<dim3(NN / 128, HH, BB), 256, AT_SMEM>>>(g_qh, g_kh, g_vh, g_gate, g_agb);

    // x1 = x + ag @ w_proj + b_proj
    mm2_kernel<0><<<dim3(CC / 128, TT / 128), 256, M2_SMEM>>>(
        g_agb, wpT, b_proj, x, nullptr, g_x1, nullptr, nullptr, nullptr,
        TT, CC, CC);

    ln_kernel<<<TT, 128>>>(g_x1, ln3_w, ln3_b, g_xn3b);

    // h = gelu(xn3 @ w_fc1 + b_fc1) -> bf16
    mm2_kernel<1><<<dim3(FF / 128, TT / 128), 256, M2_SMEM>>>(
        g_xn3b, wf1T, b_fc1, nullptr, nullptr, nullptr, g_hb, nullptr, nullptr,
        TT, FF, CC);

    // out = x1 + h @ w_fc2 + b_fc2
    mm2_kernel<0><<<dim3(CC / 128, TT / 128), 256, M2_SMEM>>>(
        g_hb, wf2T, b_fc2, g_x1, nullptr, out, nullptr, nullptr, nullptr,
        TT, CC, FF);
}

// round 17
// speedup vs baseline: 1.0427x; 1.0427x over previous
#include <cuda_runtime.h>
#include <cuda_bf16.h>
#include <math.h>
#include <cstdint>

// Problem constants
#define BB 4
#define NN 2048
#define CC 512
#define HH 8
#define DD 64
#define TT (BB*NN)          // 8192 tokens
#define FF 2048             // d_ff

// ---------------------------------------------------------------------------
// Scratch layout (float units)
#define OFF_GATE  0ull          // fp32 [TT, C]
#define OFF_X1    4194304ull    // fp32 [TT, C]
#define OFF_XE    8388608ull    // bf16 [TT, 1024]  (xn | en)
#define OFF_XN3B  12582912ull   // bf16 [TT, C]
#define OFF_AGB   14680064ull   // bf16 [TT, C]
#define OFF_HB    16777216ull   // bf16 [TT, FF]
#define OFF_WQVG  25165824ull   // bf16 [1536, 512] rows: q 0..511, v 512..1023, gate 1024..1535
#define OFF_WKS   25559040ull   // bf16 [512, 1024] cols: wkT 0..511, wsT 512..1023
#define OFF_WPT   25821184ull   // bf16 [C, C]
#define OFF_WF1T  25952256ull   // bf16 [FF, C]
#define OFF_WF2T  26476544ull   // bf16 [C, FF]
#define OFF_QH    27000832ull   // bf16 [B*H, N, 64]
#define OFF_KH    29097984ull   // bf16 [B*H, N, 64]
#define OFF_VH    31195136ull   // bf16 [B*H, N, 64]
#define SCRATCH_FLOATS 33292288ull

__device__ float g_scratch[SCRATCH_FLOATS];

// ---------------------------------------------------------------------------
__device__ __forceinline__ uint32_t smem_u32(const void* p) {
    uint32_t a;
    asm("{ .reg .u64 t; cvta.to.shared.u64 t, %1; cvt.u32.u64 %0, t; }" : "=r"(a) : "l"(p));
    return a;
}
__device__ __forceinline__ void cp_async16(uint32_t saddr, const void* gaddr) {
    asm volatile("cp.async.cg.shared.global [%0], [%1], 16;" :: "r"(saddr), "l"(gaddr) : "memory");
}
__device__ __forceinline__ void cp_commit() {
    asm volatile("cp.async.commit_group;" ::: "memory");
}
__device__ __forceinline__ void ldmx4(uint32_t& r0, uint32_t& r1, uint32_t& r2, uint32_t& r3,
                                      uint32_t addr) {
    asm volatile("ldmatrix.sync.aligned.m8n8.x4.shared.b16 {%0,%1,%2,%3}, [%4];"
                 : "=r"(r0), "=r"(r1), "=r"(r2), "=r"(r3) : "r"(addr));
}
__device__ __forceinline__ void ldmx4t(uint32_t& r0, uint32_t& r1, uint32_t& r2, uint32_t& r3,
                                       uint32_t addr) {
    asm volatile("ldmatrix.sync.aligned.m8n8.x4.trans.shared.b16 {%0,%1,%2,%3}, [%4];"
                 : "=r"(r0), "=r"(r1), "=r"(r2), "=r"(r3) : "r"(addr));
}
__device__ __forceinline__ void mma16816(float* c, const uint32_t* a, uint32_t b0, uint32_t b1) {
    asm volatile(
        "mma.sync.aligned.m16n8k16.row.col.f32.bf16.bf16.f32 "
        "{%0,%1,%2,%3}, {%4,%5,%6,%7}, {%8,%9}, {%0,%1,%2,%3};"
        : "+f"(c[0]), "+f"(c[1]), "+f"(c[2]), "+f"(c[3])
        : "r"(a[0]), "r"(a[1]), "r"(a[2]), "r"(a[3]), "r"(b0), "r"(b1));
}
__device__ __forceinline__ uint32_t pack_bf16(float a, float b) {
    __nv_bfloat162 p = __floats2bfloat162_rn(a, b);
    return *(uint32_t*)&p;
}

// ---------------------------------------------------------------------------
// Fused LayerNorm for LN1(x) and LN2(e), writing into interleaved xe buffer.
__global__ void ln2x_kernel(const float* __restrict__ x, const float* __restrict__ e,
                            const float* __restrict__ w1, const float* __restrict__ b1,
                            const float* __restrict__ w2, const float* __restrict__ b2,
                            __nv_bfloat16* __restrict__ xe) {
    int row = blockIdx.x;
    int which = blockIdx.y;
    const float* src = which ? e : x;
    const float* w   = which ? w2 : w1;
    const float* b   = which ? b2 : b1;
    __nv_bfloat16* y = xe + (size_t)row * 1024 + which * 512;
    int tid = threadIdx.x;
    const float4* xr = (const float4*)(src + (size_t)row * CC);
    float4 v = xr[tid];
    float s  = v.x + v.y + v.z + v.w;
    float ss = v.x*v.x + v.y*v.y + v.z*v.z + v.w*v.w;
    #pragma unroll
    for (int off = 16; off; off >>= 1) {
        s  += __shfl_xor_sync(0xffffffffu, s,  off);
        ss += __shfl_xor_sync(0xffffffffu, ss, off);
    }
    __shared__ float sm[4], sm2[4];
    int warp = tid >> 5, lane = tid & 31;
    if (lane == 0) { sm[warp] = s; sm2[warp] = ss; }
    __syncthreads();
    float tot  = sm[0] + sm[1] + sm[2] + sm[3];
    float tot2 = sm2[0] + sm2[1] + sm2[2] + sm2[3];
    float mu   = tot * (1.0f / CC);
    float var  = tot2 * (1.0f / CC) - mu * mu;
    float rstd = rsqrtf(var + 1e-5f);
    float4 wv = ((const float4*)w)[tid];
    float4 bv = ((const float4*)b)[tid];
    uint2 o;
    o.x = pack_bf16((v.x - mu) * rstd * wv.x + bv.x, (v.y - mu) * rstd * wv.y + bv.y);
    o.y = pack_bf16((v.z - mu) * rstd * wv.z + bv.z, (v.w - mu) * rstd * wv.w + bv.w);
    ((uint2*)y)[tid] = o;
}

// Single-tensor LN (for LN3)
__global__ void ln_kernel(const float* __restrict__ x,
                          const float* __restrict__ w,
                          const float* __restrict__ b,
                          __nv_bfloat16* __restrict__ y) {
    int row = blockIdx.x;
    int tid = threadIdx.x;
    const float4* xr = (const float4*)(x + (size_t)row * CC);
    float4 v = xr[tid];
    float s  = v.x + v.y + v.z + v.w;
    float ss = v.x*v.x + v.y*v.y + v.z*v.z + v.w*v.w;
    #pragma unroll
    for (int off = 16; off; off >>= 1) {
        s  += __shfl_xor_sync(0xffffffffu, s,  off);
        ss += __shfl_xor_sync(0xffffffffu, ss, off);
    }
    __shared__ float sm[4], sm2[4];
    int warp = tid >> 5, lane = tid & 31;
    if (lane == 0) { sm[warp] = s; sm2[warp] = ss; }
    __syncthreads();
    float tot  = sm[0] + sm[1] + sm[2] + sm[3];
    float tot2 = sm2[0] + sm2[1] + sm2[2] + sm2[3];
    float mu   = tot * (1.0f / CC);
    float var  = tot2 * (1.0f / CC) - mu * mu;
    float rstd = rsqrtf(var + 1e-5f);
    float4 wv = ((const float4*)w)[tid];
    float4 bv = ((const float4*)b)[tid];
    uint2 o;
    o.x = pack_bf16((v.x - mu) * rstd * wv.x + bv.x, (v.y - mu) * rstd * wv.y + bv.y);
    o.y = pack_bf16((v.z - mu) * rstd * wv.z + bv.z, (v.w - mu) * rstd * wv.w + bv.w);
    ((uint2*)(y + (size_t)row * CC))[tid] = o;
}

// ---------------------------------------------------------------------------
// Uber weight-transpose: all 6 weights in one launch, retargeted for the
// fused k+s layout: wqvg[1536,512] (q,v,gate rows) and wks[512,1024]
// (cols 0:512 = wkT, cols 512:1024 = wsT).
__global__ void wt_all_kernel(
    const float* __restrict__ w_qkv, const float* __restrict__ w_gate,
    const float* __restrict__ w_s,   const float* __restrict__ w_proj,
    const float* __restrict__ w_fc1, const float* __restrict__ w_fc2,
    __nv_bfloat16* __restrict__ wqvg, __nv_bfloat16* __restrict__ wks,
    __nv_bfloat16* __restrict__ wpT,  __nv_bfloat16* __restrict__ wf1T,
    __nv_bfloat16* __restrict__ wf2T)
{
    __shared__ float t[32][33];
    int tb = blockIdx.x;
    const float* W; int Nsrc, ntx, loc;
    if (tb < 768)       { W = w_qkv;  Nsrc = 1536; ntx = 48; loc = tb; }
    else if (tb < 1024) { W = w_gate; Nsrc = 512;  ntx = 16; loc = tb - 768; }
    else if (tb < 1280) { W = w_s;    Nsrc = 512;  ntx = 16; loc = tb - 1024; }
    else if (tb < 1536) { W = w_proj; Nsrc = 512;  ntx = 16; loc = tb - 1280; }
    else if (tb < 2560) { W = w_fc1;  Nsrc = 2048; ntx = 64; loc = tb - 1536; }
    else                { W = w_fc2;  Nsrc = 512;  ntx = 16; loc = tb - 2560; }
    int n0 = (loc % ntx) * 32, k0 = (loc / ntx) * 32;

    __nv_bfloat16* WT; int dn, dlda;
    if (tb < 768) {
        if (n0 < 512)       { WT = wqvg;      dn = n0;        dlda = 512; }   // q
        else if (n0 < 1024) { WT = wks;       dn = n0 - 512;  dlda = 1024; }  // k
        else                { WT = wqvg;      dn = n0 - 512;  dlda = 512; }   // v -> rows 512..1023
    }
    else if (tb < 1024) { WT = wqvg;      dn = n0 + 1024; dlda = 512; }       // gate -> rows 1024..1535
    else if (tb < 1280) { WT = wks + 512; dn = n0;        dlda = 1024; }      // s -> cols 512..1023
    else if (tb < 1536) { WT = wpT;  dn = n0; dlda = 512; }
    else if (tb < 2560) { WT = wf1T; dn = n0; dlda = 512; }
    else                { WT = wf2T; dn = n0; dlda = 2048; }

    int tx = threadIdx.x, ty = threadIdx.y;   // 32 x 8
    #pragma unroll
    for (int i = 0; i < 32; i += 8)
        t[ty + i][tx] = W[(size_t)(k0 + ty + i) * Nsrc + n0 + tx];
    __syncthreads();
    #pragma unroll
    for (int i = 0; i < 32; i += 8)
        WT[(size_t)(dn + ty + i) * dlda + k0 + tx] = __float2bfloat16(t[tx][ty + i]);
}

// ---------------------------------------------------------------------------
// mm2: HMMA bf16 GEMM, 128x128 CTA tile, 256 threads (8 warps, 2x4, 64x32
// warp tiles), BK=64 (128B rows, stride 144), 3-stage cp.async, 2 CTAs/SM.
// A has independent row stride lda (elements).
// MODE 0: fp32 out = A@Bt^T (+bias) (+res)
// MODE 1: bf16 out = gelu(A@Bt^T + bias)
// MODE 2: qvg (N=1536): seg0 q*0.125->qh(outb0), seg1 v->vh(outb1), seg2 gate fp32(outf)
// MODE 3: ks (N=512): out -> kh (outb0), per-head layout
#define M2_ROW  144
#define M2_B    18432           // A: 128 rows; B at row 128
#define M2_STG  36864           // 256 * 144
#define M2_NSTG 3
#define M2_SMEM (M2_NSTG * M2_STG)   // 110592

template<int MODE>
__global__ void __launch_bounds__(256, 2) mm2_kernel(
    const __nv_bfloat16* __restrict__ A,   // [M, lda]
    const __nv_bfloat16* __restrict__ Bt,  // [N, K]
    const float* __restrict__ bias,
    const float* __restrict__ res,
    float* __restrict__ outf,
    __nv_bfloat16* __restrict__ outb0,
    __nv_bfloat16* __restrict__ outb1,
    int M, int N, int K, int lda)
{
    extern __shared__ __align__(16) char smem[];
    uint32_t sb = smem_u32(smem);

    int tid = threadIdx.x, wid = tid >> 5, lane = tid & 31;
    int m0 = blockIdx.y * 128, n0 = blockIdx.x * 128;
    int wm = wid & 1, wn = wid >> 1;        // 2 x 4 warps, 64x32 each

    const char* Abase = (const char*)A;
    const char* Bbase = (const char*)Bt;
    size_t astride = (size_t)lda * 2;
    size_t bstride = (size_t)K * 2;
    int KC = K >> 6;   // BK = 64

    auto load_tile = [&](int kc, int stg) {
        uint32_t base = sb + stg * M2_STG;
        size_t koff = (size_t)kc * 128;
        #pragma unroll
        for (int i = 0; i < 8; i++) {
            int idx = i * 256 + tid;         // 0..2047
            int row = idx >> 3;              // 0..255
            int c = (idx & 7) * 16;
            const char* g = (row < 128)
                ? Abase + (size_t)(m0 + row) * astride + koff + c
                : Bbase + (size_t)(n0 + row - 128) * bstride + koff + c;
            cp_async16(base + row * M2_ROW + c, g);
        }
        cp_commit();
    };

    float acc[4][4][4];
    #pragma unroll
    for (int mi = 0; mi < 4; mi++)
        #pragma unroll
        for (int nb = 0; nb < 4; nb++)
            #pragma unroll
            for (int j = 0; j < 4; j++) acc[mi][nb][j] = 0.f;

    load_tile(0, 0);
    load_tile(1, 1);

    uint32_t lrow16 = (lane & 15);
    uint32_t lkhalf = (lane >> 4) * 16;

    for (int kc = 0; kc < KC; kc++) {
        if (kc < KC - 1) asm volatile("cp.async.wait_group 1;" ::: "memory");
        else             asm volatile("cp.async.wait_group 0;" ::: "memory");
        __syncthreads();

        if (kc + 2 < KC) load_tile(kc + 2, (kc + 2) % M2_NSTG);

        int stg = kc % M2_NSTG;
        uint32_t sA = sb + stg * M2_STG + (wm * 64 + lrow16) * M2_ROW + lkhalf;
        uint32_t sB = sb + stg * M2_STG + M2_B + (wn * 32 + lrow16) * M2_ROW + lkhalf;

        #pragma unroll
        for (int ks = 0; ks < 4; ks++) {
            uint32_t koff = ks * 32;
            uint32_t a[4][4];
            #pragma unroll
            for (int mi = 0; mi < 4; mi++)
                ldmx4(a[mi][0], a[mi][1], a[mi][2], a[mi][3],
                      sA + mi * 16 * M2_ROW + koff);
            uint32_t b[2][4];
            #pragma unroll
            for (int nb = 0; nb < 2; nb++)
                ldmx4(b[nb][0], b[nb][1], b[nb][2], b[nb][3],
                      sB + nb * 16 * M2_ROW + koff);
            #pragma unroll
            for (int mi = 0; mi < 4; mi++)
                #pragma unroll
                for (int nb = 0; nb < 2; nb++) {
                    mma16816(acc[mi][nb * 2 + 0], a[mi], b[nb][0], b[nb][2]);
                    mma16816(acc[mi][nb * 2 + 1], a[mi], b[nb][1], b[nb][3]);
                }
        }
        // no bottom barrier (stage overwrite is a cp.async issued after a
        // later full barrier + global-load flight time past its last read)
    }

    // ---- epilogue ----
    int mbase = m0 + wm * 64 + (lane >> 2);
    int nbase = n0 + wn * 32 + (lane & 3) * 2;
    int seg = nbase >> 9;          // uniform per warp (MODE 2)

    #pragma unroll
    for (int mi = 0; mi < 4; mi++) {
        #pragma unroll
        for (int nb = 0; nb < 4; nb++) {
            int n = nbase + nb * 8;
            #pragma unroll
            for (int half = 0; half < 2; half++) {
                int m = mbase + mi * 16 + half * 8;
                float v0 = acc[mi][nb][half * 2 + 0];
                float v1 = acc[mi][nb][half * 2 + 1];
                if (MODE == 0) {
                    if (bias) { v0 += bias[n]; v1 += bias[n + 1]; }
                    if (res) {
                        const float* rp = res + (size_t)m * N + n;
                        v0 += rp[0]; v1 += rp[1];
                    }
                    *(float2*)(outf + (size_t)m * N + n) = make_float2(v0, v1);
                } else if (MODE == 1) {
                    v0 += bias[n]; v1 += bias[n + 1];
                    v0 = 0.5f * v0 * (1.0f + erff(v0 * 0.70710678118654752f));
                    v1 = 0.5f * v1 * (1.0f + erff(v1 * 0.70710678118654752f));
                    *(uint32_t*)(outb0 + (size_t)m * N + n) = pack_bf16(v0, v1);
                } else if (MODE == 2) {
                    int c = n & 511;
                    int bidx = m >> 11, nloc = m & (NN - 1);
                    int h = c >> 6, d = c & 63;
                    size_t ph = (((size_t)(bidx * HH + h) * NN + nloc) << 6) + d;
                    if (seg == 0) {
                        *(uint32_t*)(outb0 + ph) = pack_bf16(v0 * 0.125f, v1 * 0.125f);
                    } else if (seg == 1) {
                        *(uint32_t*)(outb1 + ph) = pack_bf16(v0, v1);
                    } else {
                        *(float2*)(outf + (size_t)m * CC + c) = make_float2(v0, v1);
                    }
                } else {   // MODE 3: k+s -> kh
                    int bidx = m >> 11, nloc = m & (NN - 1);
                    int h = n >> 6, d = n & 63;
                    size_t ph = (((size_t)(bidx * HH + h) * NN + nloc) << 6) + d;
                    *(uint32_t*)(outb0 + ph) = pack_bf16(v0, v1);
                }
            }
        }
    }
}

// ---------------------------------------------------------------------------
// bf16 HMMA flash attention, fused gate-multiply epilogue (R12 champion form).
#define AT_QOFF 0
#define AT_ROW  144
#define AT_KV0  18432
#define AT_STG  18432
#define AT_SMEM (18432 + 2 * 18432)

__global__ void __launch_bounds__(256) attn_kernel(
    const __nv_bfloat16* __restrict__ qh,
    const __nv_bfloat16* __restrict__ kh,
    const __nv_bfloat16* __restrict__ vh,
    const float* __restrict__ gate,
    __nv_bfloat16* __restrict__ outb)
{
    extern __shared__ char smem[];
    uint32_t sb = smem_u32(smem);
    int tid = threadIdx.x, wid = tid >> 5, lane = tid & 31;
    int qt = blockIdx.x, h = blockIdx.y, b = blockIdx.z;
    int bh = b * HH + h;
    int tq0 = qt * 128;

    const char* Qg = (const char*)(qh + (((size_t)bh * NN + tq0) << 6));
    const char* Kg = (const char*)(kh + ((size_t)bh * NN << 6));
    const char* Vg = (const char*)(vh + ((size_t)bh * NN << 6));

    for (int i = tid; i < 1024; i += 256) {
        int r = i >> 3, c = (i & 7) * 16;
        cp_async16(sb + AT_QOFF + r * AT_ROW + c, Qg + (size_t)r * 128 + c);
    }
    cp_commit();

    auto loadKV = [&](int kt, int stg) {
        const char* K0 = Kg + ((size_t)kt << 13);
        const char* V0 = Vg + ((size_t)kt << 13);
        uint32_t ks = sb + AT_KV0 + stg * AT_STG;
        for (int i = tid; i < 512; i += 256) {
            int r = i >> 3, c = (i & 7) * 16;
            cp_async16(ks + r * AT_ROW + c, K0 + (size_t)r * 128 + c);
            cp_async16(ks + 9216 + r * AT_ROW + c, V0 + (size_t)r * 128 + c);
        }
        cp_commit();
    };

    loadKV(0, 0);
    asm volatile("cp.async.wait_group 0;" ::: "memory");
    __syncthreads();

    int r0 = wid * 16;
    uint32_t qf[4][4];
    {
        uint32_t base = sb + AT_QOFF + (r0 + (lane & 15)) * AT_ROW + (lane >> 4) * 16;
        #pragma unroll
        for (int kb = 0; kb < 4; kb++)
            ldmx4(qf[kb][0], qf[kb][1], qf[kb][2], qf[kb][3], base + kb * 32);
    }

    float o[8][4];
    #pragma unroll
    for (int nd = 0; nd < 8; nd++)
        #pragma unroll
        for (int j = 0; j < 4; j++) o[nd][j] = 0.f;
    float m0 = -1e30f, m1 = -1e30f, l0 = 0.f, l1 = 0.f;

    const int KT = NN / 64;
    for (int kt = 0; kt < KT; kt++) {
        int stg = kt & 1;
        if (kt + 1 < KT) {
            loadKV(kt + 1, stg ^ 1);
            asm volatile("cp.async.wait_group 1;" ::: "memory");
        } else {
            asm volatile("cp.async.wait_group 0;" ::: "memory");
        }
        __syncthreads();

        uint32_t Kst = sb + AT_KV0 + stg * AT_STG;
        uint32_t Vst = Kst + 9216;

        float sc[8][4];
        #pragma unroll
        for (int nb = 0; nb < 8; nb++)
            #pragma unroll
            for (int j = 0; j < 4; j++) sc[nb][j] = 0.f;

        int j2 = lane >> 3;
        int rin = lane & 7;
        #pragma unroll
        for (int p = 0; p < 4; p++) {
            #pragma unroll
            for (int kb = 0; kb < 4; kb++) {
                uint32_t addr = Kst + (p * 16 + (j2 >> 1) * 8 + rin) * AT_ROW
                                    + kb * 32 + (j2 & 1) * 16;
                uint32_t b0, b1, b2, b3;
                ldmx4(b0, b1, b2, b3, addr);
                mma16816(sc[2 * p + 0], qf[kb], b0, b1);
                mma16816(sc[2 * p + 1], qf[kb], b2, b3);
            }
        }

        float mx0 = -1e30f, mx1 = -1e30f;
        #pragma unroll
        for (int nb = 0; nb < 8; nb++) {
            mx0 = fmaxf(mx0, fmaxf(sc[nb][0], sc[nb][1]));
            mx1 = fmaxf(mx1, fmaxf(sc[nb][2], sc[nb][3]));
        }
        mx0 = fmaxf(mx0, __shfl_xor_sync(0xffffffffu, mx0, 1));
        mx0 = fmaxf(mx0, __shfl_xor_sync(0xffffffffu, mx0, 2));
        mx1 = fmaxf(mx1, __shfl_xor_sync(0xffffffffu, mx1, 1));
        mx1 = fmaxf(mx1, __shfl_xor_sync(0xffffffffu, mx1, 2));

        float mn0 = fmaxf(m0, mx0), mn1 = fmaxf(m1, mx1);
        float corr0 = __expf(m0 - mn0), corr1 = __expf(m1 - mn1);
        m0 = mn0; m1 = mn1;

        uint32_t pa[8], pb[8];
        float sum0 = 0.f, sum1 = 0.f;
        #pragma unroll
        for (int nb = 0; nb < 8; nb++) {
            float p0 = __expf(sc[nb][0] - mn0);
            float p1 = __expf(sc[nb][1] - mn0);
            float p2 = __expf(sc[nb][2] - mn1);
            float p3 = __expf(sc[nb][3] - mn1);
            sum0 += p0 + p1; sum1 += p2 + p3;
            pa[nb] = pack_bf16(p0, p1);
            pb[nb] = pack_bf16(p2, p3);
        }
        sum0 += __shfl_xor_sync(0xffffffffu, sum0, 1);
        sum0 += __shfl_xor_sync(0xffffffffu, sum0, 2);
        sum1 += __shfl_xor_sync(0xffffffffu, sum1, 1);
        sum1 += __shfl_xor_sync(0xffffffffu, sum1, 2);
        l0 = l0 * corr0 + sum0;
        l1 = l1 * corr1 + sum1;

        #pragma unroll
        for (int nd = 0; nd < 8; nd++) {
            o[nd][0] *= corr0; o[nd][1] *= corr0;
            o[nd][2] *= corr1; o[nd][3] *= corr1;
        }

        #pragma unroll
        for (int kb = 0; kb < 4; kb++) {
            uint32_t a[4] = { pa[2 * kb], pb[2 * kb], pa[2 * kb + 1], pb[2 * kb + 1] };
            #pragma unroll
            for (int v = 0; v < 4; v++) {
                uint32_t addr = Vst + (kb * 16 + (j2 & 1) * 8 + rin) * AT_ROW
                                    + v * 32 + (j2 >> 1) * 16;
                uint32_t b0, b1, b2, b3;
                ldmx4t(b0, b1, b2, b3, addr);
                mma16816(o[2 * v + 0], a, b0, b1);
                mma16816(o[2 * v + 1], a, b2, b3);
            }
        }
        __syncthreads();
    }

    float inv0 = 1.0f / l0, inv1 = 1.0f / l1;
    int rowa = tq0 + r0 + (lane >> 2);
    size_t toka = (size_t)b * NN + rowa;
    size_t tokb = toka + 8;
    int cb = h * DD + (lane & 3) * 2;
    #pragma unroll
    for (int nd = 0; nd < 8; nd++) {
        int d = cb + nd * 8;
        float2 ga = *(const float2*)(gate + toka * CC + d);
        float2 gb = *(const float2*)(gate + tokb * CC + d);
        *(uint32_t*)(outb + toka * CC + d) = pack_bf16(o[nd][0] * inv0 * ga.x,
                                                       o[nd][1] * inv0 * ga.y);
        *(uint32_t*)(outb + tokb * CC + d) = pack_bf16(o[nd][2] * inv1 * gb.x,
                                                       o[nd][3] * inv1 * gb.y);
    }
}

// ---------------------------------------------------------------------------
extern "C" void kernel_launch(void* const* d_in, const int* in_sizes, int n_in,
                              void* d_out, int out_size) {
    const float* x      = (const float*)d_in[0];
    const float* e      = (const float*)d_in[1];
    const float* w_qkv  = (const float*)d_in[2];
    const float* w_s    = (const float*)d_in[3];
    const float* w_gate = (const float*)d_in[4];
    const float* w_proj = (const float*)d_in[5];
    const float* b_proj = (const float*)d_in[6];
    const float* ln1_w  = (const float*)d_in[7];
    const float* ln1_b  = (const float*)d_in[8];
    const float* ln2_w  = (const float*)d_in[9];
    const float* ln2_b  = (const float*)d_in[10];
    const float* ln3_w  = (const float*)d_in[11];
    const float* ln3_b  = (const float*)d_in[12];
    const float* w_fc1  = (const float*)d_in[13];
    const float* b_fc1  = (const float*)d_in[14];
    const float* w_fc2  = (const float*)d_in[15];
    const float* b_fc2  = (const float*)d_in[16];
    float* out = (float*)d_out;

    void* scr_v = nullptr;
    cudaGetSymbolAddress(&scr_v, g_scratch);
    float* scr = (float*)scr_v;
    float*         g_gate = scr + OFF_GATE;
    float*         g_x1   = scr + OFF_X1;
    __nv_bfloat16* g_xe   = (__nv_bfloat16*)(scr + OFF_XE);
    __nv_bfloat16* g_xn3b = (__nv_bfloat16*)(scr + OFF_XN3B);
    __nv_bfloat16* g_agb  = (__nv_bfloat16*)(scr + OFF_AGB);
    __nv_bfloat16* g_hb   = (__nv_bfloat16*)(scr + OFF_HB);
    __nv_bfloat16* wqvg   = (__nv_bfloat16*)(scr + OFF_WQVG);
    __nv_bfloat16* wks    = (__nv_bfloat16*)(scr + OFF_WKS);
    __nv_bfloat16* wpT    = (__nv_bfloat16*)(scr + OFF_WPT);
    __nv_bfloat16* wf1T   = (__nv_bfloat16*)(scr + OFF_WF1T);
    __nv_bfloat16* wf2T   = (__nv_bfloat16*)(scr + OFF_WF2T);
    __nv_bfloat16* g_qh   = (__nv_bfloat16*)(scr + OFF_QH);
    __nv_bfloat16* g_kh   = (__nv_bfloat16*)(scr + OFF_KH);
    __nv_bfloat16* g_vh   = (__nv_bfloat16*)(scr + OFF_VH);

    cudaFuncSetAttribute(attn_kernel, cudaFuncAttributeMaxDynamicSharedMemorySize, AT_SMEM);
    cudaFuncSetAttribute(mm2_kernel<0>, cudaFuncAttributeMaxDynamicSharedMemorySize, M2_SMEM);
    cudaFuncSetAttribute(mm2_kernel<1>, cudaFuncAttributeMaxDynamicSharedMemorySize, M2_SMEM);
    cudaFuncSetAttribute(mm2_kernel<2>, cudaFuncAttributeMaxDynamicSharedMemorySize, M2_SMEM);
    cudaFuncSetAttribute(mm2_kernel<3>, cudaFuncAttributeMaxDynamicSharedMemorySize, M2_SMEM);

    // all weight transposes in one launch
    wt_all_kernel<<<3584, dim3(32, 8)>>>(w_qkv, w_gate, w_s, w_proj, w_fc1, w_fc2,
                                         wqvg, wks, wpT, wf1T, wf2T);

    // LN1(x) and LN2(e) into interleaved xe
    ln2x_kernel<<<dim3(TT, 2), 128>>>(x, e, ln1_w, ln1_b, ln2_w, ln2_b, g_xe);

    // q, v, gate GEMM (N=1536, K=512, A=xe cols 0:512, lda=1024)
    mm2_kernel<2><<<dim3(1536 / 128, TT / 128), 256, M2_SMEM>>>(
        g_xe, wqvg, nullptr, nullptr, g_gate, g_qh, g_vh,
        TT, 1536, CC, 1024);

    // k+s GEMM (N=512, K=1024, A=xe full row, lda=1024) -> kh
    mm2_kernel<3><<<dim3(CC / 128, TT / 128), 256, M2_SMEM>>>(
        g_xe, wks, nullptr, nullptr, nullptr, g_kh, nullptr,
        TT, CC, 1024, 1024);

    attn_kernel<<<dim3(NN / 128, HH, BB), 256, AT_SMEM>>>(g_qh, g_kh, g_vh, g_gate, g_agb);

    // x1 = x + ag @ w_proj + b_proj
    mm2_kernel<0><<<dim3(CC / 128, TT / 128), 256, M2_SMEM>>>(
        g_agb, wpT, b_proj, x, g_x1, nullptr, nullptr,
        TT, CC, CC, CC);

    ln_kernel<<<TT, 128>>>(g_x1, ln3_w, ln3_b, g_xn3b);

    // h = gelu(xn3 @ w_fc1 + b_fc1) -> bf16
    mm2_kernel<1><<<dim3(FF / 128, TT / 128), 256, M2_SMEM>>>(
        g_xn3b, wf1T, b_fc1, nullptr, nullptr, g_hb, nullptr,
        TT, FF, CC, CC);

    // out = x1 + h @ w_fc2 + b_fc2
    mm2_kernel<0><<<dim3(CC / 128, TT / 128), 256, M2_SMEM>>>(
        g_hb, wf2T, b_fc2, g_x1, out, nullptr, nullptr,
        TT, CC, FF, FF);
}